// round 4
// baseline (speedup 1.0000x reference)
#include <cuda_runtime.h>
#include <math.h>

// Problem constants (fixed by reference setup)
#define BD     16      // batch
#define HD     16      // heads
#define DD     128     // head dim
#define BLKD   16      // tokens per cache block
#define MAXBD  128     // blocks per sequence
#define MAXSD  2048    // max sequence length
#define NSPLIT 16      // KV splits per (b,h)
#define CHUNK  128     // tokens per split
#define NSTG   8       // stages per warp: CHUNK/4warps/4tok = 8
#define SOFTMAX_SCALE 0.088388347648318447f  // 1/sqrt(128)
#define NEGBIG (-1e30f)

// Partial-result scratch (allocation-free: __device__ globals, zero-init .bss)
__device__ float g_pm[BD * HD * NSPLIT];
__device__ float g_pl[BD * HD * NSPLIT];
__device__ float g_pacc[BD * HD * NSPLIT * DD];      // 2 MB
__device__ unsigned int g_cnt[BD * HD];              // self-resetting counters

// ---- cp.async helpers -----------------------------------------------------
__device__ __forceinline__ void cp16(void* sptr, const void* gptr) {
    unsigned s = (unsigned)__cvta_generic_to_shared(sptr);
    asm volatile("cp.async.cg.shared.global [%0], [%1], 16;" :: "r"(s), "l"(gptr));
}
__device__ __forceinline__ void cp_commit() {
    asm volatile("cp.async.commit_group;");
}
template <int N> __device__ __forceinline__ void cp_wait() {
    asm volatile("cp.async.wait_group %0;" :: "n"(N));
}

// ---------------------------------------------------------------------------
// Fused split-KV decode attention with per-warp cp.async double buffering.
//  grid (NSPLIT, HD, BD), 128 threads = 4 warps.
//  Warp w owns tokens s0+w+4k (k=0..31) in 8 stages of 4 tokens; stage data
//  (K+V rows, 4KB) is staged in SMEM via cp.async, ping-pong 2 slots, with
//  stage i+1 issued before stage i is consumed -> loads always in flight.
//  Fresh token (s == L-1) substitutes register-roped K / raw V.
//  Last split CTA per (b,h) (threadfence reduction) combines partials,
//  writes output, resets counter (graph-replay deterministic).
// ---------------------------------------------------------------------------
__global__ __launch_bounds__(128, 7) void attn_fused(
    const float* __restrict__ Q,  const float* __restrict__ K,
    const float* __restrict__ V,  const float* __restrict__ Kc,
    const float* __restrict__ Vc, const float* __restrict__ cosb,
    const float* __restrict__ sinb, const float* __restrict__ mask,
    const int* __restrict__ ilen, const int* __restrict__ btab,
    float* __restrict__ out)
{
    // [slot][warp][tok][K/V][lane] float4  = 2*4*4*2*32*16 = 32768 bytes
    __shared__ float4 buf[2][4][4][2][32];

    const int split = blockIdx.x, h = blockIdx.y, b = blockIdx.z;
    const int tid = threadIdx.x, warp = tid >> 5, lane = tid & 31;
    const int bh   = b * HD + h;
    const int pidx = bh * NSPLIT + split;
    const int L  = ilen[b];
    const int s0 = split * CHUNK;

    // combine scratch aliases into buf (used only after pipeline completes)
    float* sm_a = (float*)buf;                 // [0, 512)
    float* sm_m = (float*)buf + 512;           // [512, 516)
    float* sm_l = (float*)buf + 516;           // [516, 520)
    unsigned* s_lastp = (unsigned*)((float*)buf + 520);

    if (s0 < L) {
        const int s1  = (s0 + CHUNK < L) ? s0 + CHUNK : L;
        const int pos = L - 1;   // fresh-token position

        // --- RoPE on Q and K (registers) ---
        const float4 q4  = *(const float4*)(Q    + bh * DD + 4 * lane);
        const float4 k4  = *(const float4*)(K    + bh * DD + 4 * lane);
        const float4 vv4 = *(const float4*)(V    + bh * DD + 4 * lane);
        const float4 c4  = *(const float4*)(cosb + b * DD + 4 * lane);
        const float4 s4  = *(const float4*)(sinb + b * DD + 4 * lane);

        const float sgn = (lane < 16) ? -1.f : 1.f;   // rot = [-x2, x1]
        float4 qp, kp;
        qp.x = __shfl_xor_sync(~0u, q4.x, 16);  qp.y = __shfl_xor_sync(~0u, q4.y, 16);
        qp.z = __shfl_xor_sync(~0u, q4.z, 16);  qp.w = __shfl_xor_sync(~0u, q4.w, 16);
        kp.x = __shfl_xor_sync(~0u, k4.x, 16);  kp.y = __shfl_xor_sync(~0u, k4.y, 16);
        kp.z = __shfl_xor_sync(~0u, k4.z, 16);  kp.w = __shfl_xor_sync(~0u, k4.w, 16);

        float4 qr, kr;   // qr pre-scaled by softmax scale
        qr.x = (q4.x * c4.x + sgn * qp.x * s4.x) * SOFTMAX_SCALE;
        qr.y = (q4.y * c4.y + sgn * qp.y * s4.y) * SOFTMAX_SCALE;
        qr.z = (q4.z * c4.z + sgn * qp.z * s4.z) * SOFTMAX_SCALE;
        qr.w = (q4.w * c4.w + sgn * qp.w * s4.w) * SOFTMAX_SCALE;
        kr.x =  k4.x * c4.x + sgn * kp.x * s4.x;
        kr.y =  k4.y * c4.y + sgn * kp.y * s4.y;
        kr.z =  k4.z * c4.z + sgn * kp.z * s4.z;
        kr.w =  k4.w * c4.w + sgn * kp.w * s4.w;

        const int*   bt = btab + b * MAXBD;
        const float* mk = mask + b * MAXSD;

        float m = NEGBIG, l = 0.f;
        float4 acc = make_float4(0.f, 0.f, 0.f, 0.f);

        // ---- stage issue: 4 tokens (K+V rows) via cp.async ----
        auto issue_stage = [&](int slot, int stg) {
            #pragma unroll
            for (int j = 0; j < 4; j++) {
                const int t   = s0 + warp + 16 * stg + 4 * j;   // always < MAXSD
                const int row = __ldg(bt + (t >> 4)) * BLKD + (t & 15);
                const int off = (row * HD + h) * DD + 4 * lane;
                cp16(&buf[slot][warp][j][0][lane], Kc + off);
                cp16(&buf[slot][warp][j][1][lane], Vc + off);
            }
            cp_commit();
        };

        issue_stage(0, 0);

        #pragma unroll
        for (int stg = 0; stg < NSTG; stg++) {
            if (stg + 1 < NSTG) { issue_stage((stg + 1) & 1, stg + 1); cp_wait<1>(); }
            else                { cp_wait<0>(); }
            const int slot = stg & 1;
            const int tb   = s0 + warp + 16 * stg;

            float4 kk[4];
            #pragma unroll
            for (int j = 0; j < 4; j++) {
                kk[j] = buf[slot][warp][j][0][lane];
                if (tb + 4 * j == pos) kk[j] = kr;
            }
            float dot[4];
            #pragma unroll
            for (int j = 0; j < 4; j++)
                dot[j] = qr.x * kk[j].x + qr.y * kk[j].y
                       + qr.z * kk[j].z + qr.w * kk[j].w;
            #pragma unroll
            for (int o = 16; o > 0; o >>= 1) {
                #pragma unroll
                for (int j = 0; j < 4; j++)
                    dot[j] += __shfl_xor_sync(~0u, dot[j], o);
            }
            float sc[4];
            #pragma unroll
            for (int j = 0; j < 4; j++) {
                const int t = tb + 4 * j;
                sc[j] = (t < s1) ? dot[j] + __ldg(mk + t) : NEGBIG;
            }
            const float gm   = fmaxf(fmaxf(sc[0], sc[1]), fmaxf(sc[2], sc[3]));
            const float mnew = fmaxf(m, gm);
            const float corr = __expf(m - mnew);
            float p[4];
            #pragma unroll
            for (int j = 0; j < 4; j++) {
                p[j] = __expf(sc[j] - mnew);
                if (tb + 4 * j >= s1) p[j] = 0.f;
            }
            float4 vv[4];
            #pragma unroll
            for (int j = 0; j < 4; j++) {
                vv[j] = buf[slot][warp][j][1][lane];
                if (tb + 4 * j == pos) vv[j] = vv4;
            }
            l = l * corr + ((p[0] + p[1]) + (p[2] + p[3]));
            acc.x = acc.x * corr + (p[0]*vv[0].x + p[1]*vv[1].x + p[2]*vv[2].x + p[3]*vv[3].x);
            acc.y = acc.y * corr + (p[0]*vv[0].y + p[1]*vv[1].y + p[2]*vv[2].y + p[3]*vv[3].y);
            acc.z = acc.z * corr + (p[0]*vv[0].z + p[1]*vv[1].z + p[2]*vv[2].z + p[3]*vv[3].z);
            acc.w = acc.w * corr + (p[0]*vv[0].w + p[1]*vv[1].w + p[2]*vv[2].w + p[3]*vv[3].w);
            m = mnew;
        }

        // --- combine the 4 warps' partials (buf re-used as scratch) ---
        __syncthreads();   // all warps done with buf
        float* dst = sm_a + warp * DD + 4 * lane;
        dst[0] = acc.x; dst[1] = acc.y; dst[2] = acc.z; dst[3] = acc.w;
        if (lane == 0) { sm_m[warp] = m; sm_l[warp] = l; }
        __syncthreads();

        const float M = fmaxf(fmaxf(sm_m[0], sm_m[1]), fmaxf(sm_m[2], sm_m[3]));
        float Lt = 0.f, a = 0.f;
        #pragma unroll
        for (int w = 0; w < 4; w++) {
            const float wl = sm_l[w];
            const float wf = (wl > 0.f) ? __expf(sm_m[w] - M) : 0.f;
            Lt += wf * wl;
            a  += wf * sm_a[w * DD + tid];
        }
        if (tid == 0) { g_pm[pidx] = M; g_pl[pidx] = Lt; }
        g_pacc[pidx * DD + tid] = a;
    } else {
        // empty split: neutral partial
        if (tid == 0) { g_pm[pidx] = NEGBIG; g_pl[pidx] = 0.f; }
        g_pacc[pidx * DD + tid] = 0.f;
    }

    // --- threadfence reduction: last split CTA combines & writes output ---
    __threadfence();
    __syncthreads();
    if (tid == 0)
        *s_lastp = (atomicAdd(&g_cnt[bh], 1u) == NSPLIT - 1u) ? 1u : 0u;
    __syncthreads();

    if (*s_lastp) {
        const int base = bh * NSPLIT;
        float M = -INFINITY;
        #pragma unroll
        for (int i = 0; i < NSPLIT; i++)
            if (g_pl[base + i] > 0.f) M = fmaxf(M, g_pm[base + i]);

        float Lt = 0.f, a = 0.f;
        #pragma unroll
        for (int i = 0; i < NSPLIT; i++) {
            const float li = g_pl[base + i];
            if (li > 0.f) {
                const float w = __expf(g_pm[base + i] - M);
                Lt += w * li;
                a  += w * g_pacc[(base + i) * DD + tid];
            }
        }
        out[bh * DD + tid] = a / Lt;
        if (tid == 0) g_cnt[bh] = 0u;   // self-reset for next graph replay
    }
}

// ---------------------------------------------------------------------------
extern "C" void kernel_launch(void* const* d_in, const int* in_sizes, int n_in,
                              void* d_out, int out_size)
{
    const float* Q    = (const float*)d_in[0];
    const float* K    = (const float*)d_in[1];
    const float* V    = (const float*)d_in[2];
    const float* Kc   = (const float*)d_in[3];
    const float* Vc   = (const float*)d_in[4];
    const float* cosb = (const float*)d_in[5];
    const float* sinb = (const float*)d_in[6];
    const float* mask = (const float*)d_in[7];
    const int*   ilen = (const int*)d_in[8];
    // d_in[9] = save_slots — unused (fresh token is at input_length-1)
    const int*   btab = (const int*)d_in[10];
    (void)in_sizes; (void)n_in; (void)out_size;

    dim3 g1(NSPLIT, HD, BD);
    attn_fused<<<g1, 128>>>(Q, K, V, Kc, Vc, cosb, sinb, mask, ilen, btab,
                            (float*)d_out);
}